// round 1
// baseline (speedup 1.0000x reference)
#include <cuda_runtime.h>
#include <cuda_bf16.h>

// Problem constants (fixed shapes)
#define NN     10000
#define EE_    160000
#define NS     64
#define NV     64
#define HID    128
#define WN     320
#define KS0    192     // 2*NS + NV
#define EAD    20
#define TPS    128
#define TPV    192

#define TE     16      // edges per block
#define BT     256     // threads per block

#define INV_SQRT3 0.5773502691896258f
#define INV_SQRT2 0.7071067811865476f

// Node-precompute scratch (static device arrays; no allocation allowed)
__device__ float g_sp[NN * NS];        // silu(xs @ W_pre_s + b)
__device__ float g_vp[NN * 3 * NV];    // gated vectors, layout [n][c][v] (c-major)

__device__ __forceinline__ float siluf(float x) {
    return x / (1.0f + __expf(-x));
}

// ---------------------------------------------------------------------------
// Kernel 1: per-node precompute of gated (s_p, v_p)
// 4 nodes per 256-thread block; thread = output channel v
// ---------------------------------------------------------------------------
__global__ __launch_bounds__(256) void node_kernel(
    const float* __restrict__ x,
    const float* __restrict__ Wps, const float* __restrict__ bps,
    const float* __restrict__ Wpv,
    const float* __restrict__ gw, const float* __restrict__ gb,
    int N)
{
    __shared__ float sx[4][256];
    const int ln = threadIdx.x >> 6;      // node slot in block
    const int v  = threadIdx.x & 63;      // output channel
    const int n  = blockIdx.x * 4 + ln;

    if (n < N) {
        #pragma unroll
        for (int i = v; i < 256; i += 64) sx[ln][i] = x[n * 256 + i];
    }
    __syncthreads();
    if (n >= N) return;

    const float* xs = sx[ln];
    const float* xv = sx[ln] + 64;   // raw layout [u][c], c contiguous

    float sacc = bps[v];
    #pragma unroll 4
    for (int i = 0; i < NS; i++) sacc = fmaf(xs[i], Wps[i * NS + v], sacc);

    float ax = 0.f, ay = 0.f, az = 0.f;
    #pragma unroll 4
    for (int u = 0; u < NV; u++) {
        float w = Wpv[u * NV + v];
        ax = fmaf(xv[u * 3 + 0], w, ax);
        ay = fmaf(xv[u * 3 + 1], w, ay);
        az = fmaf(xv[u * 3 + 2], w, az);
    }
    float nrm = sqrtf(ax * ax + ay * ay + az * az + 1e-12f);
    float g = siluf(nrm * gw[v] + gb[v]);

    g_sp[n * NS + v] = siluf(sacc);
    g_vp[n * 192 + 0 * 64 + v] = ax * g;
    g_vp[n * 192 + 1 * 64 + v] = ay * g;
    g_vp[n * 192 + 2 * 64 + v] = az * g;
}

// ---------------------------------------------------------------------------
// Kernel 2: fully fused per-edge-tile layer (TE edges / block)
// smem layout (floats):
//   U    [TE*576] : phase1-3: per edge {s0[192] | h1[128] | r1[128] | pad}
//                   phase4-5: out_v as [e][c*192+u]
//   tpw  [TE*320]
//   outs [TE*128]
//   ea   [TE*20]
//   idx  [2*TE] ints
// ---------------------------------------------------------------------------
__global__ __launch_bounds__(BT, 2) void edge_kernel(
    const float* __restrict__ x,
    const float* __restrict__ edge_attr,
    const float* __restrict__ fij_in,
    const float* __restrict__ Ws1, const float* __restrict__ bs1,
    const float* __restrict__ Ws2, const float* __restrict__ bs2,
    const float* __restrict__ Wr1, const float* __restrict__ br1,
    const float* __restrict__ Wr2, const float* __restrict__ br2,
    const float* __restrict__ gwp, const float* __restrict__ gbp,
    const float* __restrict__ Wpost_s, const float* __restrict__ Wpost_v,
    const int* __restrict__ ei,
    float* __restrict__ out, int E)
{
    extern __shared__ float sm[];
    float* U    = sm;                       // TE*576
    float* tpw  = U + TE * 576;             // TE*320
    float* outs = tpw + TE * 320;           // TE*128
    float* ea   = outs + TE * 128;          // TE*20
    int*   sidx = (int*)(ea + TE * EAD);    // [src x TE][dst x TE]

    const int tid = threadIdx.x;
    const int e0  = blockIdx.x * TE;

    if (tid < TE) {
        sidx[tid]      = ei[e0 + tid];
        sidx[TE + tid] = ei[E + e0 + tid];
    }
    for (int idx = tid; idx < TE * EAD; idx += BT) {
        int e = idx / EAD, i = idx % EAD;
        ea[idx] = edge_attr[(size_t)(e0 + e) * EAD + i];
    }
    __syncthreads();

    // ---- Phase 1: build s0[e][0..191] = [xs_src | xs_dst | dot_v(raw)] ----
    for (int idx = tid; idx < TE * 64; idx += BT) {
        int e = idx >> 6, j = idx & 63;
        const float* xb_s = x + (size_t)sidx[e] * 256;
        const float* xb_d = x + (size_t)sidx[TE + e] * 256;
        U[e * 576 + j]      = xb_s[j];
        U[e * 576 + 64 + j] = xb_d[j];
        float a0 = xb_s[64 + j * 3 + 0], a1 = xb_s[64 + j * 3 + 1], a2 = xb_s[64 + j * 3 + 2];
        float b0 = xb_d[64 + j * 3 + 0], b1 = xb_d[64 + j * 3 + 1], b2 = xb_d[64 + j * 3 + 2];
        U[e * 576 + 128 + j] = a0 * b0 + a1 * b1 + a2 * b2;
    }
    __syncthreads();

    // ---- Phase 2: h1 = silu(s0@Ws1+bs1), r1 = silu(ea@Wr1+br1) ----
    {
        const int k  = tid & 127;
        const int eo = tid >> 7;   // 0 or 1
        float acc[8];
        #pragma unroll
        for (int r = 0; r < 8; r++) acc[r] = bs1[k];
        for (int i = 0; i < KS0; i += 4) {
            float w0 = Ws1[(i + 0) * HID + k];
            float w1 = Ws1[(i + 1) * HID + k];
            float w2 = Ws1[(i + 2) * HID + k];
            float w3 = Ws1[(i + 3) * HID + k];
            #pragma unroll
            for (int r = 0; r < 8; r++) {
                int e = eo + 2 * r;
                float4 s4 = *(const float4*)(U + e * 576 + i);
                acc[r] = fmaf(s4.x, w0, fmaf(s4.y, w1, fmaf(s4.z, w2, fmaf(s4.w, w3, acc[r]))));
            }
        }
        float accr[8];
        #pragma unroll
        for (int r = 0; r < 8; r++) accr[r] = br1[k];
        for (int i = 0; i < EAD; i++) {
            float w = Wr1[i * HID + k];
            #pragma unroll
            for (int r = 0; r < 8; r++)
                accr[r] = fmaf(ea[(eo + 2 * r) * EAD + i], w, accr[r]);
        }
        #pragma unroll
        for (int r = 0; r < 8; r++) {
            int e = eo + 2 * r;
            U[e * 576 + 192 + k] = siluf(acc[r]);
            U[e * 576 + 320 + k] = siluf(accr[r]);
        }
    }
    __syncthreads();

    // ---- Phase 3: tp_w = (h1@Ws2+bs2) * (r1@Wr2+br2) ----
    for (int kv = tid; kv < WN; kv += BT) {
        float acct[TE], accr[TE];
        #pragma unroll
        for (int e = 0; e < TE; e++) { acct[e] = 0.f; accr[e] = 0.f; }
        for (int i = 0; i < HID; i += 4) {
            float t0 = Ws2[(i + 0) * WN + kv];
            float t1 = Ws2[(i + 1) * WN + kv];
            float t2 = Ws2[(i + 2) * WN + kv];
            float t3 = Ws2[(i + 3) * WN + kv];
            float r0 = Wr2[(i + 0) * WN + kv];
            float r1w = Wr2[(i + 1) * WN + kv];
            float r2 = Wr2[(i + 2) * WN + kv];
            float r3 = Wr2[(i + 3) * WN + kv];
            #pragma unroll
            for (int e = 0; e < TE; e++) {
                float4 h = *(const float4*)(U + e * 576 + 192 + i);
                acct[e] = fmaf(h.x, t0, fmaf(h.y, t1, fmaf(h.z, t2, fmaf(h.w, t3, acct[e]))));
                float4 rr = *(const float4*)(U + e * 576 + 320 + i);
                accr[e] = fmaf(rr.x, r0, fmaf(rr.y, r1w, fmaf(rr.z, r2, fmaf(rr.w, r3, accr[e]))));
            }
        }
        float b2 = bs2[kv], c2 = br2[kv];
        #pragma unroll
        for (int e = 0; e < TE; e++)
            tpw[e * WN + kv] = (acct[e] + b2) * (accr[e] + c2);
    }
    __syncthreads();

    // ---- Phase 4a: out_v (gated), overwrite U as [e][c*192 + u] ----
    for (int idx = tid; idx < TE * TPV; idx += BT) {
        int e = idx / TPV, u = idx % TPV;
        int s = sidx[e], d = sidx[TE + e];
        float vx, vy, vz;
        if (u < 64) {
            float coef = tpw[e * WN + 64 + u] * g_sp[s * NS + u];     // w2 * si
            const float* vp = g_vp + d * 192;
            vx = coef * vp[u]; vy = coef * vp[64 + u]; vz = coef * vp[128 + u];
        } else if (u < 128) {
            int uu = u - 64;
            float coef = tpw[e * WN + 128 + uu] * g_sp[d * NS + uu];  // w3 * sj
            const float* vp = g_vp + s * 192;
            vx = coef * vp[uu]; vy = coef * vp[64 + uu]; vz = coef * vp[128 + uu];
        } else {
            int uu = u - 128;
            float w5 = tpw[e * WN + 256 + uu] * INV_SQRT2;
            const float* vpi = g_vp + s * 192;
            const float* vpj = g_vp + d * 192;
            float axv = vpi[uu], ayv = vpi[64 + uu], azv = vpi[128 + uu];
            float bxv = vpj[uu], byv = vpj[64 + uu], bzv = vpj[128 + uu];
            vx = w5 * (ayv * bzv - azv * byv);
            vy = w5 * (azv * bxv - axv * bzv);
            vz = w5 * (axv * byv - ayv * bxv);
        }
        float nrm = sqrtf(vx * vx + vy * vy + vz * vz + 1e-12f);
        float g = siluf(nrm * gwp[u] + gbp[u]);
        U[e * 576 + 0 * 192 + u] = vx * g;
        U[e * 576 + 1 * 192 + u] = vy * g;
        U[e * 576 + 2 * 192 + u] = vz * g;
    }

    // ---- Phase 4b: out_s = silu([w1*si*sj | w4*dot(vi,vj)/sqrt3]) ----
    for (int idx = tid; idx < TE * TPS; idx += BT) {
        int e = idx >> 7, j = idx & 127;
        int s = sidx[e], d = sidx[TE + e];
        float val;
        if (j < 64) {
            val = tpw[e * WN + j] * g_sp[s * NS + j] * g_sp[d * NS + j];
        } else {
            int u = j - 64;
            const float* vpi = g_vp + s * 192;
            const float* vpj = g_vp + d * 192;
            float dt = vpi[u] * vpj[u] + vpi[64 + u] * vpj[64 + u] + vpi[128 + u] * vpj[128 + u];
            val = tpw[e * WN + 192 + u] * dt * INV_SQRT3;
        }
        outs[e * TPS + j] = siluf(val);
    }
    __syncthreads();

    // ---- Phase 5a: fij_s = out_s @ W_post_s ; += fij_in ; store ----
    {
        const int v  = tid & 63;
        const int eo = tid >> 6;   // 0..3
        float acc[4];
        #pragma unroll
        for (int g4 = 0; g4 < 4; g4++) acc[g4] = 0.f;
        for (int j = 0; j < TPS; j += 4) {
            float w0 = Wpost_s[(j + 0) * NS + v];
            float w1 = Wpost_s[(j + 1) * NS + v];
            float w2 = Wpost_s[(j + 2) * NS + v];
            float w3 = Wpost_s[(j + 3) * NS + v];
            #pragma unroll
            for (int g4 = 0; g4 < 4; g4++) {
                int e = eo + 4 * g4;
                float4 o4 = *(const float4*)(outs + e * TPS + j);
                acc[g4] = fmaf(o4.x, w0, fmaf(o4.y, w1, fmaf(o4.z, w2, fmaf(o4.w, w3, acc[g4]))));
            }
        }
        #pragma unroll
        for (int g4 = 0; g4 < 4; g4++) {
            int e = eo + 4 * g4;
            size_t o = (size_t)(e0 + e) * 256 + v;
            out[o] = fij_in[o] + acc[g4];
        }
    }

    // ---- Phase 5b: fij_v[v][c] = sum_u out_v[u][c] * W_post_v[u][v] ; += fij_in ----
    {
        const int v = tid & 63;
        const int g = tid >> 6;    // 0..3 -> 12 (e,c) pairs each
        float acc[12];
        #pragma unroll
        for (int p = 0; p < 12; p++) acc[p] = 0.f;
        for (int u = 0; u < TPV; u += 4) {
            float w0 = Wpost_v[(u + 0) * NV + v];
            float w1 = Wpost_v[(u + 1) * NV + v];
            float w2 = Wpost_v[(u + 2) * NV + v];
            float w3 = Wpost_v[(u + 3) * NV + v];
            #pragma unroll
            for (int p = 0; p < 12; p++) {
                int e = g * 4 + p / 3;
                int c = p % 3;
                float4 ov = *(const float4*)(U + e * 576 + c * 192 + u);
                acc[p] = fmaf(ov.x, w0, fmaf(ov.y, w1, fmaf(ov.z, w2, fmaf(ov.w, w3, acc[p]))));
            }
        }
        #pragma unroll
        for (int p = 0; p < 12; p++) {
            int e = g * 4 + p / 3;
            int c = p % 3;
            size_t o = (size_t)(e0 + e) * 256 + 64 + (size_t)v * 3 + c;
            out[o] = fij_in[o] + acc[p];
        }
    }
}

// ---------------------------------------------------------------------------
extern "C" void kernel_launch(void* const* d_in, const int* in_sizes, int n_in,
                              void* d_out, int out_size)
{
    const float* x         = (const float*)d_in[0];
    const float* edge_attr = (const float*)d_in[1];
    const float* fij_in    = (const float*)d_in[2];
    const float* W_pre_s   = (const float*)d_in[3];
    const float* b_pre_s   = (const float*)d_in[4];
    const float* W_pre_v   = (const float*)d_in[5];
    const float* gw_pre    = (const float*)d_in[6];
    const float* gb_pre    = (const float*)d_in[7];
    const float* Ws1       = (const float*)d_in[8];
    const float* bs1       = (const float*)d_in[9];
    const float* Ws2       = (const float*)d_in[10];
    const float* bs2       = (const float*)d_in[11];
    const float* Wr1       = (const float*)d_in[12];
    const float* br1       = (const float*)d_in[13];
    const float* Wr2       = (const float*)d_in[14];
    const float* br2       = (const float*)d_in[15];
    const float* gw_post   = (const float*)d_in[16];
    const float* gb_post   = (const float*)d_in[17];
    const float* W_post_s  = (const float*)d_in[18];
    const float* W_post_v  = (const float*)d_in[19];
    const int*   ei        = (const int*)d_in[20];

    const int N = in_sizes[0] / 256;
    const int E = in_sizes[2] / 256;

    node_kernel<<<(N + 3) / 4, 256>>>(x, W_pre_s, b_pre_s, W_pre_v, gw_pre, gb_pre, N);

    const size_t shm = (size_t)(TE * 576 + TE * 320 + TE * 128 + TE * EAD) * 4 + TE * 2 * 4;
    cudaFuncSetAttribute(edge_kernel, cudaFuncAttributeMaxDynamicSharedMemorySize, (int)shm);

    edge_kernel<<<E / TE, BT, shm>>>(
        x, edge_attr, fij_in,
        Ws1, bs1, Ws2, bs2, Wr1, br1, Wr2, br2,
        gw_post, gb_post, W_post_s, W_post_v,
        ei, (float*)d_out, E);
}